// round 14
// baseline (speedup 1.0000x reference)
#include <cuda_runtime.h>
#include <cstdint>

// VTBPR fused kernel (R14): fully warp-autonomous rows.
//   score[b] = item_beta[i] + user_beta[u] + <ug,ig> + <tv,vf_b> + <tt,tf_b>
//   metapath[b,0,p,l,:] = ug if path_type==0, ig if ==1, else 0
//
// d_out = [ score (B floats) | metapath (B*16*512 floats) ]
//
// One WARP per batch row (4 rows per 128-thread CTA, grid=2048). Each
// thread owns 4 float4 lanes (c = lane + 32k). Consequences:
//  - dot reduction is pure intra-warp shuffle: ZERO smem, ZERO barriers
//  - path_type held in one register/lane, broadcast via __shfl_sync
//  - no cross-warp coupling anywhere: each row's 38KB of traffic flows
//    independently (R12/R13 showed barrier skew-coupling costs real time)
// Registers phased: ug/ig live through the scatter; tv/vf then tt/tf
// phases reuse the same registers. Occupancy proven irrelevant (26-88%).

#define HIDDEN 512
#define PL     16
#define NT     128            // 4 warps = 4 rows per CTA
#define RPC    4

__global__ void __launch_bounds__(NT)
vtbpr_kernel(const float* __restrict__ user_gama,
             const float* __restrict__ item_gama,
             const float* __restrict__ user_beta,
             const float* __restrict__ item_beta,
             const float* __restrict__ theta_user_visual,
             const float* __restrict__ theta_user_text,
             const float* __restrict__ visual_features,
             const float* __restrict__ textural_features,
             const int*   __restrict__ user_idx,
             const int*   __restrict__ item_idx,
             const int*   __restrict__ path_type,
             float* __restrict__ out,
             int B)
{
    const int wid  = threadIdx.x >> 5;       // warp 0..3 = row within CTA
    const int lane = threadIdx.x & 31;
    const int b    = blockIdx.x * RPC + wid;

    const int u = user_idx[b];
    const int i = item_idx[b];

    // Lane j (<16) holds path_type[b][j]; broadcast later via shfl.
    int ptv = 0;
    if (lane < PL) ptv = path_type[b * PL + lane];

    const float4* ug_p = (const float4*)(user_gama         + (size_t)u * HIDDEN);
    const float4* ig_p = (const float4*)(item_gama         + (size_t)i * HIDDEN);
    const float4* tv_p = (const float4*)(theta_user_visual + (size_t)u * HIDDEN);
    const float4* tt_p = (const float4*)(theta_user_text   + (size_t)u * HIDDEN);
    const float4* vf_p = (const float4*)(visual_features   + (size_t)b * HIDDEN);
    const float4* tf_p = (const float4*)(textural_features + (size_t)b * HIDDEN);

    // ---- Phase 1: ug/ig (kept live through the scatter) ----
    float4 ug4[4], ig4[4];
    #pragma unroll
    for (int k = 0; k < 4; k++) ug4[k] = ug_p[lane + 32 * k];
    #pragma unroll
    for (int k = 0; k < 4; k++) ig4[k] = ig_p[lane + 32 * k];

    float partial = 0.f;
    #pragma unroll
    for (int k = 0; k < 4; k++)
        partial += ug4[k].x * ig4[k].x + ug4[k].y * ig4[k].y +
                   ug4[k].z * ig4[k].z + ug4[k].w * ig4[k].w;

    // ---- Metapath scatter: 16 segments x 4 STG.128/thread, coalesced ----
    float4* mp = (float4*)(out + B + (size_t)b * PL * HIDDEN);
    const float4 zero4 = make_float4(0.f, 0.f, 0.f, 0.f);

    #pragma unroll
    for (int j = 0; j < PL; j++) {
        const int t = __shfl_sync(0xFFFFFFFFu, ptv, j);
        float4* seg = mp + (size_t)j * (HIDDEN / 4);
        if (t == 0) {
            #pragma unroll
            for (int k = 0; k < 4; k++) seg[lane + 32 * k] = ug4[k];
        } else if (t == 1) {
            #pragma unroll
            for (int k = 0; k < 4; k++) seg[lane + 32 * k] = ig4[k];
        } else {
            #pragma unroll
            for (int k = 0; k < 4; k++) seg[lane + 32 * k] = zero4;
        }
    }

    // ---- Phase 2: tv/vf (registers of ug/ig now dead) ----
    #pragma unroll
    for (int k = 0; k < 4; k++) {
        const float4 a = tv_p[lane + 32 * k];
        const float4 c = vf_p[lane + 32 * k];
        partial += a.x * c.x + a.y * c.y + a.z * c.z + a.w * c.w;
    }

    // ---- Phase 3: tt/tf ----
    #pragma unroll
    for (int k = 0; k < 4; k++) {
        const float4 a = tt_p[lane + 32 * k];
        const float4 c = tf_p[lane + 32 * k];
        partial += a.x * c.x + a.y * c.y + a.z * c.z + a.w * c.w;
    }

    // ---- Intra-warp reduce + score (no smem, no barrier) ----
    #pragma unroll
    for (int off = 16; off > 0; off >>= 1)
        partial += __shfl_xor_sync(0xFFFFFFFFu, partial, off);

    if (lane == 0)
        out[b] = partial + user_beta[u] + item_beta[i];
}

extern "C" void kernel_launch(void* const* d_in, const int* in_sizes, int n_in,
                              void* d_out, int out_size)
{
    const float* user_gama          = (const float*)d_in[0];
    const float* item_gama          = (const float*)d_in[1];
    const float* user_beta          = (const float*)d_in[2];
    const float* item_beta          = (const float*)d_in[3];
    const float* theta_user_visual  = (const float*)d_in[4];
    const float* theta_user_text    = (const float*)d_in[5];
    const float* visual_features    = (const float*)d_in[6];
    const float* textural_features  = (const float*)d_in[7];
    const int*   user_idx           = (const int*)d_in[8];
    const int*   item_idx           = (const int*)d_in[9];
    const int*   path_type          = (const int*)d_in[10];

    const int B = in_sizes[8];  // 8192 (divisible by 4)

    vtbpr_kernel<<<B / RPC, NT>>>(user_gama, item_gama, user_beta, item_beta,
                                  theta_user_visual, theta_user_text,
                                  visual_features, textural_features,
                                  user_idx, item_idx, path_type,
                                  (float*)d_out, B);
}

// round 15
// speedup vs baseline: 1.0726x; 1.0726x over previous
#include <cuda_runtime.h>
#include <cstdint>

// VTBPR fused kernel (FINAL = R13): 2 rows per 256-thread CTA, per-row
// named barriers, evict_last reads.
//   score[b] = item_beta[i] + user_beta[u] + <ug,ig> + <tv,vf_b> + <tt,tf_b>
//   metapath[b,0,p,l,:] = ug if path_type==0, ig if ==1, else 0
//
// d_out = [ score (B floats) | metapath (B*16*512 floats) ]
//
// Sweep results (R2-R14): kernel is pinned at the DRAM mixed-stream
// ceiling (~5.5TB/s on 268MB writes + ~42MB read misses). Invariant to:
// occupancy (26-88%), store path (STG/UBLKCP), L2 policy (.cs/.wt/
// evict_last), store ordering. Structural optimum bracketed: 128
// threads/row (R14's 32 lost), 2 rows/CTA (R12's 4 lost), per-row
// named barriers (beats CTA-wide sync). This configuration measured
// best: 59.87us wall / 56.38us ncu.

#define HIDDEN 512
#define VEC    (HIDDEN / 4)   // 128 float4 lanes per row
#define PL     16             // P*L
#define NT     256            // threads per CTA (2 rows)

__device__ __forceinline__ uint64_t policy_evict_last() {
    uint64_t p;
    asm("createpolicy.fractional.L2::evict_last.b64 %0, 1.0;" : "=l"(p));
    return p;
}

__device__ __forceinline__ float4 ld_el(const float4* a, uint64_t pol) {
    float4 v;
    asm("ld.global.L2::cache_hint.v4.f32 {%0,%1,%2,%3}, [%4], %5;"
        : "=f"(v.x), "=f"(v.y), "=f"(v.z), "=f"(v.w)
        : "l"(a), "l"(pol));
    return v;
}

__global__ void __launch_bounds__(NT, 4)
vtbpr_kernel(const float* __restrict__ user_gama,
             const float* __restrict__ item_gama,
             const float* __restrict__ user_beta,
             const float* __restrict__ item_beta,
             const float* __restrict__ theta_user_visual,
             const float* __restrict__ theta_user_text,
             const float* __restrict__ visual_features,
             const float* __restrict__ textural_features,
             const int*   __restrict__ user_idx,
             const int*   __restrict__ item_idx,
             const int*   __restrict__ path_type,
             float* __restrict__ out,
             int B)
{
    const int tid  = threadIdx.x;          // 0..255
    const int half = tid >> 7;             // 0/1: which row this half owns
    const int lane = tid & (VEC - 1);      // 0..127 within the row
    const int b    = blockIdx.x * 2 + half;

    __shared__ int   pt[2][PL];
    __shared__ float wsum[2][VEC / 32];

    const int u = user_idx[b];
    const int i = item_idx[b];

    // Each half stages its OWN row's path types (lanes 0..15 of the half).
    if (lane < PL) pt[half][lane] = path_type[b * PL + lane];
    const float ub = user_beta[u];
    const float ib = item_beta[i];

    const uint64_t pol = policy_evict_last();

    const float4* ug_p = (const float4*)(user_gama         + (size_t)u * HIDDEN);
    const float4* ig_p = (const float4*)(item_gama         + (size_t)i * HIDDEN);
    const float4* tv_p = (const float4*)(theta_user_visual + (size_t)u * HIDDEN);
    const float4* tt_p = (const float4*)(theta_user_text   + (size_t)u * HIDDEN);
    const float4* vf_p = (const float4*)(visual_features   + (size_t)b * HIDDEN);
    const float4* tf_p = (const float4*)(textural_features + (size_t)b * HIDDEN);

    // Front-batch all six vector loads (max MLP), pinned evict_last in L2.
    const float4 ug4 = ld_el(&ug_p[lane], pol);
    const float4 ig4 = ld_el(&ig_p[lane], pol);
    const float4 tv4 = ld_el(&tv_p[lane], pol);
    const float4 tt4 = ld_el(&tt_p[lane], pol);
    const float4 vf4 = ld_el(&vf_p[lane], pol);
    const float4 tf4 = ld_el(&tf_p[lane], pol);

    // Dot products + warp reduce
    float partial =
        ug4.x * ig4.x + ug4.y * ig4.y + ug4.z * ig4.z + ug4.w * ig4.w +
        tv4.x * vf4.x + tv4.y * vf4.y + tv4.z * vf4.z + tv4.w * vf4.w +
        tt4.x * tf4.x + tt4.y * tf4.y + tt4.z * tf4.z + tt4.w * tf4.w;

    #pragma unroll
    for (int off = 16; off > 0; off >>= 1)
        partial += __shfl_xor_sync(0xFFFFFFFFu, partial, off);

    if ((tid & 31) == 0) wsum[half][(tid >> 5) & 3] = partial;

    // Per-row barrier: only this row's 4 warps synchronize (pt + wsum).
    asm volatile("bar.sync %0, %1;" :: "r"(1 + half), "r"(VEC) : "memory");

    if (lane == 0) {
        float s = ub + ib;
        #pragma unroll
        for (int w = 0; w < VEC / 32; w++) s += wsum[half][w];
        out[b] = s;
    }

    // Metapath scatter: 16 coalesced STG.128 per thread for this row.
    float4* mp = (float4*)(out + B + (size_t)b * PL * HIDDEN);
    const float4 zero4 = make_float4(0.f, 0.f, 0.f, 0.f);

    #pragma unroll
    for (int j = 0; j < PL; j++) {
        const int t = pt[half][j];
        const float4 v = (t == 0) ? ug4 : ((t == 1) ? ig4 : zero4);
        mp[(size_t)j * VEC + lane] = v;
    }
}

extern "C" void kernel_launch(void* const* d_in, const int* in_sizes, int n_in,
                              void* d_out, int out_size)
{
    const float* user_gama          = (const float*)d_in[0];
    const float* item_gama          = (const float*)d_in[1];
    const float* user_beta          = (const float*)d_in[2];
    const float* item_beta          = (const float*)d_in[3];
    const float* theta_user_visual  = (const float*)d_in[4];
    const float* theta_user_text    = (const float*)d_in[5];
    const float* visual_features    = (const float*)d_in[6];
    const float* textural_features  = (const float*)d_in[7];
    const int*   user_idx           = (const int*)d_in[8];
    const int*   item_idx           = (const int*)d_in[9];
    const int*   path_type          = (const int*)d_in[10];

    const int B = in_sizes[8];  // 8192 (even)

    vtbpr_kernel<<<B / 2, NT>>>(user_gama, item_gama, user_beta, item_beta,
                                theta_user_visual, theta_user_text,
                                visual_features, textural_features,
                                user_idx, item_idx, path_type,
                                (float*)d_out, B);
}